// round 12
// baseline (speedup 1.0000x reference)
#include <cuda_runtime.h>

// Adaptive threshold spike encoding — write-through store-policy probe.
// x: [B=32, F=65536] f32.  out: [B=32, T=32, F=65536] f32.
//
// Identical to the floor kernel (2048x256, one float4/thread, 32 regs,
// exact-fit grid, unrolled T=32) except stores use st.global.wt (__stwt).
// Purpose: falsify the one unverified leg of the floor model — that dirty-
// line writeback makes each output byte transit LTS twice. Write-through
// lines are never dirty; if the writeback-read was a real separate cost,
// this gains up to ~20%. If neutral/worse, the ~42 us LTS-cap floor is
// confirmed final and R10 is the committed kernel.

#define TIMESTEPS 32
#define F_DIM 65536
#define F4_DIM (F_DIM / 4)      // 16384 float4 per feature row
#define RATE 0.1f
#define OMR 0.9f
#define THR0 0.5f
#define THREADS 256

__global__ __launch_bounds__(THREADS)
void adaptive_threshold_kernel(const float4* __restrict__ x,
                               float4* __restrict__ out) {
    int i = blockIdx.x * THREADS + threadIdx.x;   // float4 index (exact fit)

    float4 xv = __ldcs(&x[i]);

    // element index -> (batch, feature4)
    int e  = i << 2;                 // element index of lane 0 of this float4
    int b  = e >> 16;                // batch = e / 65536
    int f4 = (e & (F_DIM - 1)) >> 2; // float4 slot within the feature row

    float xx[4] = {xv.x, xv.y, xv.z, xv.w};
    float ad[4], acc[4], thr[4];
#pragma unroll
    for (int l = 0; l < 4; l++) {
        ad[l]  = RATE * fabsf(xx[l]);
        acc[l] = 0.0f;
        thr[l] = THR0;
    }

    // out[b][t][f]: base of this (b, f4) column, stride F4_DIM per timestep
    float4* ob = out + (size_t)b * (TIMESTEPS * F4_DIM) + f4;

#pragma unroll
    for (int t = 0; t < TIMESTEPS; t++) {
        float s[4];
#pragma unroll
        for (int l = 0; l < 4; l++) {
            acc[l] = acc[l] + xx[l];
            bool m = (acc[l] >= thr[l]);
            s[l]   = m ? 1.0f : 0.0f;
            acc[l] = m ? 0.0f : acc[l];
            thr[l] = thr[l] * OMR + ad[l];
        }
        float4 sv;
        sv.x = s[0]; sv.y = s[1]; sv.z = s[2]; sv.w = s[3];
        __stwt(ob + (size_t)t * F4_DIM, sv);   // write-through
    }
}

extern "C" void kernel_launch(void* const* d_in, const int* in_sizes, int n_in,
                              void* d_out, int out_size) {
    const float4* x = (const float4*)d_in[0];
    float4* out = (float4*)d_out;
    int n4 = in_sizes[0] / 4;              // 524,288 — divisible by THREADS
    int blocks = n4 / THREADS;             // 2048
    adaptive_threshold_kernel<<<blocks, THREADS>>>(x, out);
}

// round 13
// speedup vs baseline: 1.0358x; 1.0358x over previous
#include <cuda_runtime.h>

// Adaptive threshold spike encoding — FINAL (measured machine floor; R10
// config: best run kernel 41.63 us, wall 45.50 us, 5.22 TB/s DRAM).
// x: [B=32, F=65536] f32.  out: [B=32, T=32, F=65536] f32.
//
// Closed model, 12 rounds / 7 configs:
//   - Fixed traffic: 256 MB write + 8 MB read (output bytes set by problem).
//   - Binding resource: LTS write path (SM-clock domain), ~6300 B/cyc
//     path-independent cap; fill + writeback accounting gives 520 MB /
//     41.6 us ~= 12.5 TB/s at NAT clock.
//   - Store-policy dimension fully probed: STG 42.0 / .cs 41.6-42.5 /
//     TMA bulk 41.8 / .wt 43.1 us — every GMEM write path transits LTS
//     identically; writeback leg not separately removable.
//   - Shape dimension fully probed: occ 51-95%, issue 12-35%, block
//     256/512, grid 1024/1184/2048 — no effect. Persistent grid and
//     8-elem threads only regressed.
//   - DVFS-throttled replay slowed proportionally to SM clock at constant
//     cycle count -> not DRAM-device bound.
//   => ~80K cycles (~42 us kernel / ~45.5 us wall) is the hard floor.
//
// Shape: 2048 blocks x 256 threads, one float4 per thread, 32 regs,
// exact-fit grid (no bounds check), coalesced STG.128 evict-first stores,
// fully unrolled 32-timestep loop (pure FFMA/FSEL recurrence, no spills).

#define TIMESTEPS 32
#define F_DIM 65536
#define F4_DIM (F_DIM / 4)      // 16384 float4 per feature row
#define RATE 0.1f
#define OMR 0.9f
#define THR0 0.5f
#define THREADS 256

__global__ __launch_bounds__(THREADS)
void adaptive_threshold_kernel(const float4* __restrict__ x,
                               float4* __restrict__ out) {
    int i = blockIdx.x * THREADS + threadIdx.x;   // float4 index (exact fit)

    float4 xv = __ldcs(&x[i]);

    // element index -> (batch, feature4)
    int e  = i << 2;                 // element index of lane 0 of this float4
    int b  = e >> 16;                // batch = e / 65536
    int f4 = (e & (F_DIM - 1)) >> 2; // float4 slot within the feature row

    float xx[4] = {xv.x, xv.y, xv.z, xv.w};
    float ad[4], acc[4], thr[4];
#pragma unroll
    for (int l = 0; l < 4; l++) {
        ad[l]  = RATE * fabsf(xx[l]);
        acc[l] = 0.0f;
        thr[l] = THR0;
    }

    // out[b][t][f]: base of this (b, f4) column, stride F4_DIM per timestep
    float4* ob = out + (size_t)b * (TIMESTEPS * F4_DIM) + f4;

#pragma unroll
    for (int t = 0; t < TIMESTEPS; t++) {
        float s[4];
#pragma unroll
        for (int l = 0; l < 4; l++) {
            acc[l] = acc[l] + xx[l];
            bool m = (acc[l] >= thr[l]);
            s[l]   = m ? 1.0f : 0.0f;
            acc[l] = m ? 0.0f : acc[l];
            thr[l] = thr[l] * OMR + ad[l];
        }
        float4 sv;
        sv.x = s[0]; sv.y = s[1]; sv.z = s[2]; sv.w = s[3];
        __stcs(ob + (size_t)t * F4_DIM, sv);
    }
}

extern "C" void kernel_launch(void* const* d_in, const int* in_sizes, int n_in,
                              void* d_out, int out_size) {
    const float4* x = (const float4*)d_in[0];
    float4* out = (float4*)d_out;
    int n4 = in_sizes[0] / 4;              // 524,288 — divisible by THREADS
    int blocks = n4 / THREADS;             // 2048
    adaptive_threshold_kernel<<<blocks, THREADS>>>(x, out);
}